// round 4
// baseline (speedup 1.0000x reference)
#include <cuda_runtime.h>
#include <math.h>

#define NB 16384
#define ND 4096
#define NH 128
#define NE 64
#define NS 5

#define SCALE_F 1.4285714626312256f   // float32(1/0.7)
#define PDROP_F 0.3f
#define UNC_T   0.3f

// scratch for hidden activations (16384 x 128 fp32 = 8 MB)
__device__ float g_h[NB * NH];

// ---------------------------------------------------------------------------
// Kernel 1: h = relu(x @ W1 + b1)
// M-tile 128, N = 128 (full H), K-tile 16. 256 threads, 8x8 per thread.
// Double-buffered smem with register staging.
// ---------------------------------------------------------------------------
__global__ __launch_bounds__(256, 1)
void gemm1_kernel(const float* __restrict__ x,
                  const float* __restrict__ W1,
                  const float* __restrict__ b1)
{
    __shared__ float As[2][16][132];   // [buf][k][m]  (transposed A)
    __shared__ float Bs[2][16][128];   // [buf][k][n]

    const int tid = threadIdx.x;
    const int ty  = tid >> 4;          // 0..15 -> rows ty*8..
    const int tx  = tid & 15;          // 0..15 -> cols tx*8..
    const int m0  = blockIdx.x * 128;

    float acc[8][8];
#pragma unroll
    for (int i = 0; i < 8; i++)
#pragma unroll
        for (int j = 0; j < 8; j++) acc[i][j] = 0.f;

    // A loads: 512 float4/tile, thread handles idx=tid and idx=tid+256
    const int a_row0 = tid >> 2;           // 0..63
    const int a_c4   = tid & 3;            // 0..3
    const int a_row1 = a_row0 + 64;
    // B loads: idx=tid -> (krow=tid>>5, col4=tid&31); idx=tid+256 -> krow+8
    const int b_k    = tid >> 5;           // 0..7
    const int b_c4   = tid & 31;           // 0..31

    const float* xa0 = x + (size_t)(m0 + a_row0) * ND + a_c4 * 4;
    const float* xa1 = x + (size_t)(m0 + a_row1) * ND + a_c4 * 4;
    const float* wb0 = W1 + (size_t)b_k * NH + b_c4 * 4;
    const float* wb1 = W1 + (size_t)(b_k + 8) * NH + b_c4 * 4;

    float4 fa0, fa1, fb0, fb1;

    // preload tile 0
    fa0 = *(const float4*)(xa0);
    fa1 = *(const float4*)(xa1);
    fb0 = *(const float4*)(wb0);
    fb1 = *(const float4*)(wb1);
    {
        As[0][a_c4*4+0][a_row0] = fa0.x; As[0][a_c4*4+1][a_row0] = fa0.y;
        As[0][a_c4*4+2][a_row0] = fa0.z; As[0][a_c4*4+3][a_row0] = fa0.w;
        As[0][a_c4*4+0][a_row1] = fa1.x; As[0][a_c4*4+1][a_row1] = fa1.y;
        As[0][a_c4*4+2][a_row1] = fa1.z; As[0][a_c4*4+3][a_row1] = fa1.w;
        *(float4*)&Bs[0][b_k    ][b_c4*4] = fb0;
        *(float4*)&Bs[0][b_k + 8][b_c4*4] = fb1;
    }
    __syncthreads();

    const int nIter = ND / 16;   // 256
    for (int t = 0; t < nIter; t++) {
        const int cur = t & 1;
        if (t + 1 < nIter) {
            const int kk = (t + 1) * 16;
            fa0 = *(const float4*)(xa0 + kk);
            fa1 = *(const float4*)(xa1 + kk);
            fb0 = *(const float4*)(wb0 + (size_t)kk * NH);
            fb1 = *(const float4*)(wb1 + (size_t)kk * NH);
        }
#pragma unroll
        for (int k = 0; k < 16; k++) {
            float a[8], b[8];
#pragma unroll
            for (int i = 0; i < 8; i++) a[i] = As[cur][k][ty*8 + i];
#pragma unroll
            for (int j = 0; j < 8; j++) b[j] = Bs[cur][k][tx*8 + j];
#pragma unroll
            for (int i = 0; i < 8; i++)
#pragma unroll
                for (int j = 0; j < 8; j++)
                    acc[i][j] = fmaf(a[i], b[j], acc[i][j]);
        }
        __syncthreads();
        if (t + 1 < nIter) {
            const int nxt = cur ^ 1;
            As[nxt][a_c4*4+0][a_row0] = fa0.x; As[nxt][a_c4*4+1][a_row0] = fa0.y;
            As[nxt][a_c4*4+2][a_row0] = fa0.z; As[nxt][a_c4*4+3][a_row0] = fa0.w;
            As[nxt][a_c4*4+0][a_row1] = fa1.x; As[nxt][a_c4*4+1][a_row1] = fa1.y;
            As[nxt][a_c4*4+2][a_row1] = fa1.z; As[nxt][a_c4*4+3][a_row1] = fa1.w;
            *(float4*)&Bs[nxt][b_k    ][b_c4*4] = fb0;
            *(float4*)&Bs[nxt][b_k + 8][b_c4*4] = fb1;
        }
        __syncthreads();
    }

    // epilogue: bias + relu -> g_h
#pragma unroll
    for (int i = 0; i < 8; i++) {
        const int r = m0 + ty*8 + i;
#pragma unroll
        for (int j = 0; j < 8; j += 4) {
            float4 v;
            v.x = fmaxf(acc[i][j+0] + b1[tx*8 + j+0], 0.f);
            v.y = fmaxf(acc[i][j+1] + b1[tx*8 + j+1], 0.f);
            v.z = fmaxf(acc[i][j+2] + b1[tx*8 + j+2], 0.f);
            v.w = fmaxf(acc[i][j+3] + b1[tx*8 + j+3], 0.f);
            *(float4*)&g_h[(size_t)r * NH + tx*8 + j] = v;
        }
    }
}

// ---------------------------------------------------------------------------
// Kernel 2: per-row routing. One warp per row, 4 rows per 128-thread block.
// Each lane owns 2 of the 64 expert columns.
// ---------------------------------------------------------------------------
__global__ __launch_bounds__(128, 1)
void routing_kernel(const float* __restrict__ W2,
                    const float* __restrict__ b2,
                    const float* __restrict__ m1,
                    const float* __restrict__ m2,
                    float* __restrict__ out)
{
    __shared__ float W2s[NH * NE];        // 32 KB
    __shared__ float hm[4][NS][NH];       // 10 KB

    const int tid  = threadIdx.x;
    const int warp = tid >> 5;
    const int lane = tid & 31;

    // stage W2 (128x64) into smem
    for (int i = tid; i < NH * NE / 4; i += 128)
        ((float4*)W2s)[i] = ((const float4*)W2)[i];
    __syncthreads();

    const int row = blockIdx.x * 4 + warp;

    // per-sample dropout-scaled hidden: hm[s][h] = h[h] * mask1 * scale
    for (int idx = lane; idx < NS * NH; idx += 32) {
        const int s  = idx >> 7;
        const int hh = idx & 127;
        const float hv = g_h[(size_t)row * NH + hh];
        const float u  = m1[(size_t)s * NB * NH + (size_t)row * NH + hh];
        hm[warp][s][hh] = (u >= PDROP_F) ? hv * SCALE_F : 0.f;
    }
    __syncwarp();

    const int e0 = lane * 2;

    // logits[s][e0], logits[s][e0+1]
    float lg[NS][2];
#pragma unroll
    for (int s = 0; s < NS; s++) { lg[s][0] = 0.f; lg[s][1] = 0.f; }

    const float* hmw = &hm[warp][0][0];
#pragma unroll 4
    for (int hh = 0; hh < NH; hh++) {
        const float2 w = *(const float2*)&W2s[hh * NE + e0];
#pragma unroll
        for (int s = 0; s < NS; s++) {
            const float hv = hmw[s * NH + hh];
            lg[s][0] = fmaf(hv, w.x, lg[s][0]);
            lg[s][1] = fmaf(hv, w.y, lg[s][1]);
        }
    }

    // + b2, then dropout mask2 * scale
    const float b20 = b2[e0], b21 = b2[e0 + 1];
#pragma unroll
    for (int s = 0; s < NS; s++) {
        float u0 = m2[(size_t)s * NB * NE + (size_t)row * NE + e0];
        float u1 = m2[(size_t)s * NB * NE + (size_t)row * NE + e0 + 1];
        lg[s][0] = (u0 >= PDROP_F) ? (lg[s][0] + b20) * SCALE_F : 0.f;
        lg[s][1] = (u1 >= PDROP_F) ? (lg[s][1] + b21) * SCALE_F : 0.f;
    }

    // mean logits -> softmax (probs)
    float ml0 = 0.f, ml1 = 0.f;
#pragma unroll
    for (int s = 0; s < NS; s++) { ml0 += lg[s][0]; ml1 += lg[s][1]; }
    ml0 *= 0.2f; ml1 *= 0.2f;

    float mx = fmaxf(ml0, ml1);
#pragma unroll
    for (int o = 16; o; o >>= 1) mx = fmaxf(mx, __shfl_xor_sync(~0u, mx, o));
    float p0 = __expf(ml0 - mx), p1 = __expf(ml1 - mx);
    float sm = p0 + p1;
#pragma unroll
    for (int o = 16; o; o >>= 1) sm += __shfl_xor_sync(~0u, sm, o);
    const float inv = 1.f / sm;
    p0 *= inv; p1 *= inv;

    // per-sample softmax
    float ap[NS][2];
#pragma unroll
    for (int s = 0; s < NS; s++) {
        float a0 = lg[s][0], a1 = lg[s][1];
        float m = fmaxf(a0, a1);
#pragma unroll
        for (int o = 16; o; o >>= 1) m = fmaxf(m, __shfl_xor_sync(~0u, m, o));
        float e0v = __expf(a0 - m), e1v = __expf(a1 - m);
        float s2 = e0v + e1v;
#pragma unroll
        for (int o = 16; o; o >>= 1) s2 += __shfl_xor_sync(~0u, s2, o);
        const float iv = 1.f / s2;
        ap[s][0] = e0v * iv; ap[s][1] = e1v * iv;
    }

    // uncertainty = mean_e( std_s(ap, ddof=1) )
    float up = 0.f;
#pragma unroll
    for (int j = 0; j < 2; j++) {
        float mean = 0.f;
#pragma unroll
        for (int s = 0; s < NS; s++) mean += ap[s][j];
        mean *= 0.2f;
        float var = 0.f;
#pragma unroll
        for (int s = 0; s < NS; s++) {
            const float d = ap[s][j] - mean;
            var = fmaf(d, d, var);
        }
        up += sqrtf(var * 0.25f);
    }
#pragma unroll
    for (int o = 16; o; o >>= 1) up += __shfl_xor_sync(~0u, up, o);
    const float unc = up * (1.f / 64.f);

    // top-4 (descending, ties -> lower index, matching jax.lax.top_k)
    float v0 = p0, v1 = p1;
    float selp[4]; int seli[4];
#pragma unroll
    for (int t = 0; t < 4; t++) {
        float bv; int bi;
        if (v0 >= v1) { bv = v0; bi = e0; } else { bv = v1; bi = e0 + 1; }
#pragma unroll
        for (int o = 16; o; o >>= 1) {
            const float ov = __shfl_xor_sync(~0u, bv, o);
            const int   oi = __shfl_xor_sync(~0u, bi, o);
            if (ov > bv || (ov == bv && oi < bi)) { bv = ov; bi = oi; }
        }
        selp[t] = bv; seli[t] = bi;
        if (bi == e0)          v0 = -1.f;
        else if (bi == e0 + 1) v1 = -1.f;
    }

    if (lane == 0) {
        const bool un = unc > UNC_T;
        // output layout: [idx (B,4)] [probs (B,4)] [uncertainty (B)]
        out[row*4 + 0] = (float)seli[0];
        out[row*4 + 1] = (float)seli[1];
        out[row*4 + 2] = un ? (float)seli[2] : -1.f;
        out[row*4 + 3] = un ? (float)seli[3] : -1.f;
        float* op = out + (size_t)NB * 4;
        op[row*4 + 0] = selp[0];
        op[row*4 + 1] = selp[1];
        op[row*4 + 2] = un ? selp[2] : 0.f;
        op[row*4 + 3] = un ? selp[3] : 0.f;
        out[(size_t)NB * 8 + row] = unc;
    }
}

// ---------------------------------------------------------------------------
extern "C" void kernel_launch(void* const* d_in, const int* in_sizes, int n_in,
                              void* d_out, int out_size)
{
    const float* x  = (const float*)d_in[0];
    const float* W1 = (const float*)d_in[1];
    const float* b1 = (const float*)d_in[2];
    const float* W2 = (const float*)d_in[3];
    const float* b2 = (const float*)d_in[4];
    const float* m1 = (const float*)d_in[5];
    const float* m2 = (const float*)d_in[6];
    float* out = (float*)d_out;

    gemm1_kernel<<<NB / 128, 256>>>(x, W1, b1);
    routing_kernel<<<NB / 4, 128>>>(W2, b2, m1, m2, out);
}

// round 11
// speedup vs baseline: 2.3759x; 2.3759x over previous
#include <cuda_runtime.h>
#include <cuda_bf16.h>
#include <stdint.h>
#include <math.h>

#define NB 16384
#define ND 4096
#define NH 128
#define NE 64
#define NS 5

#define SCALE_F 1.4285714626312256f   // float32(1/0.7)
#define PDROP_F 0.3f
#define UNC_T   0.3f

// scratch
__device__ float         g_h[NB * NH];         // hidden activations (8 MB)
__device__ __nv_bfloat16 g_w1t_hi[NH * ND];    // W1^T hi split (1 MB)
__device__ __nv_bfloat16 g_w1t_lo[NH * ND];    // W1^T lo split (1 MB)

// ---------------------------------------------------------------------------
// mma.sync m16n8k16 bf16 (standard PTX, valid on base sm_103 target)
// ---------------------------------------------------------------------------
#define MMA16816(c, a, b) \
    asm volatile("mma.sync.aligned.m16n8k16.row.col.f32.bf16.bf16.f32 " \
        "{%0,%1,%2,%3}, {%4,%5,%6,%7}, {%8,%9}, {%0,%1,%2,%3};" \
        : "+f"((c)[0]), "+f"((c)[1]), "+f"((c)[2]), "+f"((c)[3]) \
        : "r"((a)[0]), "r"((a)[1]), "r"((a)[2]), "r"((a)[3]), \
          "r"((b)[0]), "r"((b)[1]))

// swizzled byte offset of (row, kbyte) in a [rows][128B] tile.
// XOR mask depends only on row; all within-row k offsets stay < 128.
__device__ __forceinline__ uint32_t swrow(uint32_t row, uint32_t kb) {
    return row * 128u + (kb ^ ((row & 7u) << 4));
}

// ---------------------------------------------------------------------------
// Kernel 0: split-transpose W1 [D,H] fp32 -> W1t hi/lo [H,D] bf16
// ---------------------------------------------------------------------------
__global__ void w1split_kernel(const float* __restrict__ W1)
{
    int idx = blockIdx.x * 256 + threadIdx.x;     // over ND*NH
    int k = idx >> 7;        // D index
    int n = idx & 127;       // H index
    float v = W1[idx];
    uint32_t u = __float_as_uint(v);
    g_w1t_hi[(size_t)n * ND + k] = __ushort_as_bfloat16((unsigned short)(u >> 16));
    float lo = v - __uint_as_float(u & 0xffff0000u);
    g_w1t_lo[(size_t)n * ND + k] = __float2bfloat16_rn(lo);
}

// ---------------------------------------------------------------------------
// Kernel 1: HMMA bf16 3-split GEMM: h = relu(x @ W1 + b1)
// CTA tile 128x128, K-chunk 64, 256 threads (8 warps, warp tile 32x64),
// double-buffered smem, register-staged prefetch.
// ---------------------------------------------------------------------------
#define OFF_AHI 0
#define OFF_ALO 16384
#define OFF_BHI 32768
#define OFF_BLO 49152
#define STAGE_BYTES 65536
#define GEMM_SMEM (2 * STAGE_BYTES)   // 131072

__global__ __launch_bounds__(256, 1)
void gemm1_hmma(const float* __restrict__ x, const float* __restrict__ b1)
{
    extern __shared__ __align__(1024) char smem[];
    const int tid  = threadIdx.x;
    const int wid  = tid >> 5;
    const int lane = tid & 31;
    const int m0   = blockIdx.x * 128;

    const int qr = lane >> 2;           // 0..7
    const uint32_t qc = (lane & 3) * 4; // byte offset of the k-pair (bit4 == 0)
    const int wm = (wid & 3) * 32;      // warp M offset in CTA tile
    const int wn = (wid >> 2) * 64;     // warp N offset

    // global load pointers (8 A-float4, 4 B-hi, 4 B-lo float4 per thread/chunk)
    const float*         xA  = x + (size_t)(m0 + (tid >> 4)) * ND + (tid & 15) * 4;
    const __nv_bfloat16* bHp = g_w1t_hi + (size_t)(tid >> 3) * ND + (tid & 7) * 8;
    const __nv_bfloat16* bLp = g_w1t_lo + (size_t)(tid >> 3) * ND + (tid & 7) * 8;

    float acc[2][8][4];
#pragma unroll
    for (int mf = 0; mf < 2; mf++)
#pragma unroll
        for (int nf = 0; nf < 8; nf++)
#pragma unroll
            for (int c = 0; c < 4; c++) acc[mf][nf][c] = 0.f;

    float4 av[8], bh[4], bl[4];

    // ---- load chunk 0 into regs
#pragma unroll
    for (int j = 0; j < 8; j++) av[j] = *(const float4*)(xA + (size_t)j * 16 * ND);
#pragma unroll
    for (int j = 0; j < 4; j++) bh[j] = *(const float4*)(bHp + (size_t)j * 32 * ND);
#pragma unroll
    for (int j = 0; j < 4; j++) bl[j] = *(const float4*)(bLp + (size_t)j * 32 * ND);

    // store-staged-registers helper (A split fp32->bf16 hi/lo inline)
#define STORE_STAGE(TILE)                                                        \
    do {                                                                         \
        char* t = (TILE);                                                        \
        _Pragma("unroll")                                                        \
        for (int j = 0; j < 8; j++) {                                            \
            uint32_t row = (uint32_t)(tid >> 4) + j * 16;                        \
            uint32_t so  = swrow(row, (uint32_t)(tid & 15) * 8);                 \
            float4 v = av[j];                                                    \
            uint32_t ux = __float_as_uint(v.x), uy = __float_as_uint(v.y);       \
            uint32_t uz = __float_as_uint(v.z), uw = __float_as_uint(v.w);       \
            uint32_t hi01 = __byte_perm(ux, uy, 0x7632);                         \
            uint32_t hi23 = __byte_perm(uz, uw, 0x7632);                         \
            float lx = v.x - __uint_as_float(ux & 0xffff0000u);                  \
            float ly = v.y - __uint_as_float(uy & 0xffff0000u);                  \
            float lz = v.z - __uint_as_float(uz & 0xffff0000u);                  \
            float lw = v.w - __uint_as_float(uw & 0xffff0000u);                  \
            __nv_bfloat162 l01 = __floats2bfloat162_rn(lx, ly);                  \
            __nv_bfloat162 l23 = __floats2bfloat162_rn(lz, lw);                  \
            *(uint2*)(t + OFF_AHI + so) = make_uint2(hi01, hi23);                \
            *(uint2*)(t + OFF_ALO + so) =                                        \
                make_uint2(*(uint32_t*)&l01, *(uint32_t*)&l23);                  \
        }                                                                        \
        _Pragma("unroll")                                                        \
        for (int j = 0; j < 4; j++) {                                            \
            uint32_t row = (uint32_t)(tid >> 3) + j * 32;                        \
            uint32_t so  = swrow(row, (uint32_t)(tid & 7) * 16);                 \
            *(float4*)(t + OFF_BHI + so) = bh[j];                                \
            *(float4*)(t + OFF_BLO + so) = bl[j];                                \
        }                                                                        \
    } while (0)

    STORE_STAGE(smem);
    __syncthreads();

    const int nChunk = ND / 64;   // 64
#pragma unroll 1
    for (int i = 0; i < nChunk; i++) {
        // prefetch chunk i+1 into regs (overlaps with compute below)
        if (i + 1 < nChunk) {
            const int k0 = (i + 1) * 64;
#pragma unroll
            for (int j = 0; j < 8; j++) av[j] = *(const float4*)(xA + (size_t)j * 16 * ND + k0);
#pragma unroll
            for (int j = 0; j < 4; j++) bh[j] = *(const float4*)(bHp + (size_t)j * 32 * ND + k0);
#pragma unroll
            for (int j = 0; j < 4; j++) bl[j] = *(const float4*)(bLp + (size_t)j * 32 * ND + k0);
        }

        char* tile = smem + (i & 1) * STAGE_BYTES;
        char* tAH = tile + OFF_AHI;
        char* tAL = tile + OFF_ALO;
        char* tBH = tile + OFF_BHI;
        char* tBL = tile + OFF_BLO;

#pragma unroll
        for (int ks = 0; ks < 4; ks++) {
            const uint32_t kb = (uint32_t)ks * 32 + qc;   // bit4 always 0

            uint32_t ah[2][4], al[2][4];
#pragma unroll
            for (int mf = 0; mf < 2; mf++) {
                uint32_t row = (uint32_t)(wm + mf * 16 + qr);
                uint32_t so  = swrow(row, kb);
                uint32_t so2 = so ^ 16;      // swrow(row, kb+16): XOR, not add!
                ah[mf][0] = *(uint32_t*)(tAH + so);
                ah[mf][1] = *(uint32_t*)(tAH + so + 1024);
                ah[mf][2] = *(uint32_t*)(tAH + so2);
                ah[mf][3] = *(uint32_t*)(tAH + so2 + 1024);
                al[mf][0] = *(uint32_t*)(tAL + so);
                al[mf][1] = *(uint32_t*)(tAL + so + 1024);
                al[mf][2] = *(uint32_t*)(tAL + so2);
                al[mf][3] = *(uint32_t*)(tAL + so2 + 1024);
            }
            uint32_t bhf[8][2], blf[8][2];
#pragma unroll
            for (int nf = 0; nf < 8; nf++) {
                uint32_t row = (uint32_t)(wn + nf * 8 + qr);
                uint32_t so  = swrow(row, kb);
                uint32_t so2 = so ^ 16;
                bhf[nf][0] = *(uint32_t*)(tBH + so);
                bhf[nf][1] = *(uint32_t*)(tBH + so2);
                blf[nf][0] = *(uint32_t*)(tBL + so);
                blf[nf][1] = *(uint32_t*)(tBL + so2);
            }
#pragma unroll
            for (int mf = 0; mf < 2; mf++)
#pragma unroll
                for (int nf = 0; nf < 8; nf++) {
                    MMA16816(acc[mf][nf], ah[mf], bhf[nf]);
                    MMA16816(acc[mf][nf], ah[mf], blf[nf]);
                    MMA16816(acc[mf][nf], al[mf], bhf[nf]);
                }
        }

        __syncthreads();
        if (i + 1 < nChunk) {
            STORE_STAGE(smem + ((i + 1) & 1) * STAGE_BYTES);
            __syncthreads();
        }
    }

    // epilogue: bias + relu -> g_h
#pragma unroll
    for (int nf = 0; nf < 8; nf++) {
        const int n = wn + nf * 8 + (lane & 3) * 2;
        const float bn0 = b1[n], bn1 = b1[n + 1];
#pragma unroll
        for (int mf = 0; mf < 2; mf++) {
            const int m = m0 + wm + mf * 16 + qr;
            float2 v0, v1;
            v0.x = fmaxf(acc[mf][nf][0] + bn0, 0.f);
            v0.y = fmaxf(acc[mf][nf][1] + bn1, 0.f);
            v1.x = fmaxf(acc[mf][nf][2] + bn0, 0.f);
            v1.y = fmaxf(acc[mf][nf][3] + bn1, 0.f);
            *(float2*)&g_h[(size_t)m * NH + n]       = v0;
            *(float2*)&g_h[(size_t)(m + 8) * NH + n] = v1;
        }
    }
#undef STORE_STAGE
}

// ---------------------------------------------------------------------------
// Kernel 2: routing. One warp per row, 16 rows per 512-thread block.
// Dynamic smem: W2 (32KB) + hm (40KB) = 72KB, 3 CTAs/SM.
// ---------------------------------------------------------------------------
#define ROUT_SMEM ((NH * NE + 16 * NS * NH) * 4)   // 73728

__global__ __launch_bounds__(512, 3)
void routing_kernel(const float* __restrict__ W2,
                    const float* __restrict__ b2,
                    const float* __restrict__ m1,
                    const float* __restrict__ m2,
                    float* __restrict__ out)
{
    extern __shared__ float rsm[];
    float* W2s = rsm;                 // [NH*NE]
    float* hm  = rsm + NH * NE;       // [16][NS][NH]

    const int tid  = threadIdx.x;
    const int warp = tid >> 5;
    const int lane = tid & 31;

    for (int i = tid; i < NH * NE / 4; i += 512)
        ((float4*)W2s)[i] = ((const float4*)W2)[i];
    __syncthreads();

    const int row = blockIdx.x * 16 + warp;
    float* hw = hm + warp * (NS * NH);

    for (int idx = lane; idx < NS * NH; idx += 32) {
        const int s  = idx >> 7;
        const int hh = idx & 127;
        const float hv = g_h[(size_t)row * NH + hh];
        const float u  = m1[(size_t)s * NB * NH + (size_t)row * NH + hh];
        hw[idx] = (u >= PDROP_F) ? hv * SCALE_F : 0.f;
    }
    __syncwarp();

    const int e0 = lane * 2;

    float lg[NS][2];
#pragma unroll
    for (int s = 0; s < NS; s++) { lg[s][0] = 0.f; lg[s][1] = 0.f; }

#pragma unroll 4
    for (int hh = 0; hh < NH; hh++) {
        const float2 w = *(const float2*)&W2s[hh * NE + e0];
#pragma unroll
        for (int s = 0; s < NS; s++) {
            const float hv = hw[s * NH + hh];
            lg[s][0] = fmaf(hv, w.x, lg[s][0]);
            lg[s][1] = fmaf(hv, w.y, lg[s][1]);
        }
    }

    const float b20 = b2[e0], b21 = b2[e0 + 1];
#pragma unroll
    for (int s = 0; s < NS; s++) {
        float u0 = m2[(size_t)s * NB * NE + (size_t)row * NE + e0];
        float u1 = m2[(size_t)s * NB * NE + (size_t)row * NE + e0 + 1];
        lg[s][0] = (u0 >= PDROP_F) ? (lg[s][0] + b20) * SCALE_F : 0.f;
        lg[s][1] = (u1 >= PDROP_F) ? (lg[s][1] + b21) * SCALE_F : 0.f;
    }

    // mean logits -> softmax
    float ml0 = 0.f, ml1 = 0.f;
#pragma unroll
    for (int s = 0; s < NS; s++) { ml0 += lg[s][0]; ml1 += lg[s][1]; }
    ml0 *= 0.2f; ml1 *= 0.2f;

    float mx = fmaxf(ml0, ml1);
#pragma unroll
    for (int o = 16; o; o >>= 1) mx = fmaxf(mx, __shfl_xor_sync(~0u, mx, o));
    float p0 = __expf(ml0 - mx), p1 = __expf(ml1 - mx);
    float sm = p0 + p1;
#pragma unroll
    for (int o = 16; o; o >>= 1) sm += __shfl_xor_sync(~0u, sm, o);
    const float inv = 1.f / sm;
    p0 *= inv; p1 *= inv;

    // per-sample softmax
    float ap[NS][2];
#pragma unroll
    for (int s = 0; s < NS; s++) {
        float a0 = lg[s][0], a1 = lg[s][1];
        float m = fmaxf(a0, a1);
#pragma unroll
        for (int o = 16; o; o >>= 1) m = fmaxf(m, __shfl_xor_sync(~0u, m, o));
        float e0v = __expf(a0 - m), e1v = __expf(a1 - m);
        float s2 = e0v + e1v;
#pragma unroll
        for (int o = 16; o; o >>= 1) s2 += __shfl_xor_sync(~0u, s2, o);
        const float iv = 1.f / s2;
        ap[s][0] = e0v * iv; ap[s][1] = e1v * iv;
    }

    // uncertainty = mean_e( std_s(ap, ddof=1) )
    float up = 0.f;
#pragma unroll
    for (int j = 0; j < 2; j++) {
        float mean = 0.f;
#pragma unroll
        for (int s = 0; s < NS; s++) mean += ap[s][j];
        mean *= 0.2f;
        float var = 0.f;
#pragma unroll
        for (int s = 0; s < NS; s++) {
            const float d = ap[s][j] - mean;
            var = fmaf(d, d, var);
        }
        up += sqrtf(var * 0.25f);
    }
#pragma unroll
    for (int o = 16; o; o >>= 1) up += __shfl_xor_sync(~0u, up, o);
    const float unc = up * (1.f / 64.f);

    // top-4 (desc, ties -> lower index)
    float v0 = p0, v1 = p1;
    float selp[4]; int seli[4];
#pragma unroll
    for (int t = 0; t < 4; t++) {
        float bv; int bi;
        if (v0 >= v1) { bv = v0; bi = e0; } else { bv = v1; bi = e0 + 1; }
#pragma unroll
        for (int o = 16; o; o >>= 1) {
            const float ov = __shfl_xor_sync(~0u, bv, o);
            const int   oi = __shfl_xor_sync(~0u, bi, o);
            if (ov > bv || (ov == bv && oi < bi)) { bv = ov; bi = oi; }
        }
        selp[t] = bv; seli[t] = bi;
        if (bi == e0)          v0 = -1.f;
        else if (bi == e0 + 1) v1 = -1.f;
    }

    if (lane == 0) {
        const bool un = unc > UNC_T;
        out[row * 4 + 0] = (float)seli[0];
        out[row * 4 + 1] = (float)seli[1];
        out[row * 4 + 2] = un ? (float)seli[2] : -1.f;
        out[row * 4 + 3] = un ? (float)seli[3] : -1.f;
        float* op = out + (size_t)NB * 4;
        op[row * 4 + 0] = selp[0];
        op[row * 4 + 1] = selp[1];
        op[row * 4 + 2] = un ? selp[2] : 0.f;
        op[row * 4 + 3] = un ? selp[3] : 0.f;
        out[(size_t)NB * 8 + row] = unc;
    }
}

// ---------------------------------------------------------------------------
extern "C" void kernel_launch(void* const* d_in, const int* in_sizes, int n_in,
                              void* d_out, int out_size)
{
    const float* x  = (const float*)d_in[0];
    const float* W1 = (const float*)d_in[1];
    const float* b1 = (const float*)d_in[2];
    const float* W2 = (const float*)d_in[3];
    const float* b2 = (const float*)d_in[4];
    const float* m1 = (const float*)d_in[5];
    const float* m2 = (const float*)d_in[6];
    float* out = (float*)d_out;

    cudaFuncSetAttribute(gemm1_hmma, cudaFuncAttributeMaxDynamicSharedMemorySize, GEMM_SMEM);
    cudaFuncSetAttribute(routing_kernel, cudaFuncAttributeMaxDynamicSharedMemorySize, ROUT_SMEM);

    w1split_kernel<<<(ND * NH) / 256, 256>>>(W1);
    gemm1_hmma<<<NB / 128, 256, GEMM_SMEM>>>(x, b1);
    routing_kernel<<<NB / 16, 512, ROUT_SMEM>>>(W2, b2, m1, m2, out);
}

// round 14
// speedup vs baseline: 2.6368x; 1.1098x over previous
#include <cuda_runtime.h>
#include <cuda_bf16.h>
#include <stdint.h>
#include <math.h>

#define NB 16384
#define ND 4096
#define NH 128
#define NE 64
#define NS 5

#define SCALE_F 1.4285714626312256f   // float32(1/0.7)
#define PDROP_F 0.3f
#define UNC_T   0.3f

// scratch
__device__ float         g_h[NB * NH];         // hidden activations (8 MB)
__device__ __nv_bfloat16 g_w1t_hi[NH * ND];    // W1^T hi split (1 MB)
__device__ __nv_bfloat16 g_w1t_lo[NH * ND];    // W1^T lo split (1 MB)

// ---------------------------------------------------------------------------
// PTX helpers (standard ISA, valid on base sm_103 target)
// ---------------------------------------------------------------------------
#define MMA16816(c, a, b) \
    asm volatile("mma.sync.aligned.m16n8k16.row.col.f32.bf16.bf16.f32 " \
        "{%0,%1,%2,%3}, {%4,%5,%6,%7}, {%8,%9}, {%0,%1,%2,%3};" \
        : "+f"((c)[0]), "+f"((c)[1]), "+f"((c)[2]), "+f"((c)[3]) \
        : "r"((a)[0]), "r"((a)[1]), "r"((a)[2]), "r"((a)[3]), \
          "r"((b)[0]), "r"((b)[1]))

#define LDSM4(r0, r1, r2, r3, addr) \
    asm volatile("ldmatrix.sync.aligned.m8n8.x4.shared.b16 {%0,%1,%2,%3}, [%4];" \
        : "=r"(r0), "=r"(r1), "=r"(r2), "=r"(r3) : "r"(addr))

__device__ __forceinline__ uint32_t smem_u32(const void* p) {
    uint32_t a;
    asm("{ .reg .u64 t; cvta.to.shared.u64 t, %1; cvt.u32.u64 %0, t; }" : "=r"(a) : "l"(p));
    return a;
}

// swizzled byte offset of (row, kbyte) in a [rows][128B] tile.
// XOR mask depends only on row; all within-row k offsets stay < 128.
__device__ __forceinline__ uint32_t swrow(uint32_t row, uint32_t kb) {
    return row * 128u + (kb ^ ((row & 7u) << 4));
}

// ---------------------------------------------------------------------------
// Kernel 0: split-transpose W1 [D,H] fp32 -> W1t hi/lo [H,D] bf16
// 32x32 smem tile transpose: coalesced loads AND coalesced 4B stores.
// ---------------------------------------------------------------------------
__global__ void w1split_kernel(const float* __restrict__ W1)
{
    __shared__ unsigned short thi[32][33];
    __shared__ unsigned short tlo[32][33];
    const int k0 = blockIdx.x * 32;     // D tile
    const int n0 = blockIdx.y * 32;     // H tile
    const int c  = threadIdx.x & 31;
    const int r0 = threadIdx.x >> 5;    // 0..7

#pragma unroll
    for (int j = 0; j < 4; j++) {
        const int r = r0 + j * 8;
        float v = W1[(size_t)(k0 + r) * NH + n0 + c];
        uint32_t u = __float_as_uint(v);
        thi[r][c] = (unsigned short)(u >> 16);
        float lo = v - __uint_as_float(u & 0xffff0000u);
        __nv_bfloat16 lb = __float2bfloat16_rn(lo);
        tlo[r][c] = *(unsigned short*)&lb;
    }
    __syncthreads();

    const int c2 = threadIdx.x & 15;    // k-pair within tile
    const int r1 = threadIdx.x >> 4;    // 0..15
#pragma unroll
    for (int j = 0; j < 2; j++) {
        const int n = r1 + j * 16;
        uint32_t hi = (uint32_t)thi[c2 * 2][n] | ((uint32_t)thi[c2 * 2 + 1][n] << 16);
        uint32_t lo = (uint32_t)tlo[c2 * 2][n] | ((uint32_t)tlo[c2 * 2 + 1][n] << 16);
        *(uint32_t*)&g_w1t_hi[(size_t)(n0 + n) * ND + k0 + c2 * 2] = hi;
        *(uint32_t*)&g_w1t_lo[(size_t)(n0 + n) * ND + k0 + c2 * 2] = lo;
    }
}

// ---------------------------------------------------------------------------
// Kernel 1: HMMA bf16 3-split GEMM: h = relu(x @ W1 + b1)
// CTA tile 128x128, K-chunk 64, 256 threads (8 warps, warp tile 32x64),
// double-buffered smem, register-staged prefetch, ldmatrix fragment loads.
// ---------------------------------------------------------------------------
#define OFF_AHI 0
#define OFF_ALO 16384
#define OFF_BHI 32768
#define OFF_BLO 49152
#define STAGE_BYTES 65536
#define GEMM_SMEM (2 * STAGE_BYTES)   // 131072

__global__ __launch_bounds__(256, 1)
void gemm1_hmma(const float* __restrict__ x, const float* __restrict__ b1)
{
    extern __shared__ __align__(1024) char smem[];
    const uint32_t sbase = smem_u32(smem);
    const int tid  = threadIdx.x;
    const int wid  = tid >> 5;
    const int lane = tid & 31;
    const int m0   = blockIdx.x * 128;

    const int qr = lane >> 2;           // 0..7 (acc row within 8)
    const int wm = (wid & 3) * 32;      // warp M offset in CTA tile
    const int wn = (wid >> 2) * 64;     // warp N offset

    // ldmatrix lane geometry (mask identical for A and B: row&7 == lane&7)
    const uint32_t mask   = (uint32_t)(lane & 7) << 4;
    const uint32_t kselA  = (lane & 16) ? 16u : 0u;   // A: m2,m3 -> k+8
    const uint32_t kselB  = (lane & 8)  ? 16u : 0u;   // B: m1,m3 -> k+8
    const uint32_t rowA0  = (uint32_t)(wm + (lane & 7) + ((lane & 8) ? 8 : 0));
    const uint32_t rowB0  = (uint32_t)(wn + (lane & 7) + ((lane & 16) ? 8 : 0));
    const uint32_t aoff0  = rowA0 * 128u;
    const uint32_t aoff1  = aoff0 + 16u * 128u;       // mf=1
    uint32_t boff[4];
#pragma unroll
    for (int p = 0; p < 4; p++) boff[p] = (rowB0 + p * 16u) * 128u;

    // global load pointers (8 A-float4, 4 B-hi, 4 B-lo float4 per thread/chunk)
    const float*         xA  = x + (size_t)(m0 + (tid >> 4)) * ND + (tid & 15) * 4;
    const __nv_bfloat16* bHp = g_w1t_hi + (size_t)(tid >> 3) * ND + (tid & 7) * 8;
    const __nv_bfloat16* bLp = g_w1t_lo + (size_t)(tid >> 3) * ND + (tid & 7) * 8;

    float acc[2][8][4];
#pragma unroll
    for (int mf = 0; mf < 2; mf++)
#pragma unroll
        for (int nf = 0; nf < 8; nf++)
#pragma unroll
            for (int c = 0; c < 4; c++) acc[mf][nf][c] = 0.f;

    float4 av[8], bh[4], bl[4];

    // ---- load chunk 0 into regs
#pragma unroll
    for (int j = 0; j < 8; j++) av[j] = *(const float4*)(xA + (size_t)j * 16 * ND);
#pragma unroll
    for (int j = 0; j < 4; j++) bh[j] = *(const float4*)(bHp + (size_t)j * 32 * ND);
#pragma unroll
    for (int j = 0; j < 4; j++) bl[j] = *(const float4*)(bLp + (size_t)j * 32 * ND);

    // store-staged-registers helper (A split fp32->bf16 hi/lo inline)
#define STORE_STAGE(TILE)                                                        \
    do {                                                                         \
        char* t = (TILE);                                                        \
        _Pragma("unroll")                                                        \
        for (int j = 0; j < 8; j++) {                                            \
            uint32_t row = (uint32_t)(tid >> 4) + j * 16;                        \
            uint32_t so  = swrow(row, (uint32_t)(tid & 15) * 8);                 \
            float4 v = av[j];                                                    \
            uint32_t ux = __float_as_uint(v.x), uy = __float_as_uint(v.y);       \
            uint32_t uz = __float_as_uint(v.z), uw = __float_as_uint(v.w);       \
            uint32_t hi01 = __byte_perm(ux, uy, 0x7632);                         \
            uint32_t hi23 = __byte_perm(uz, uw, 0x7632);                         \
            float lx = v.x - __uint_as_float(ux & 0xffff0000u);                  \
            float ly = v.y - __uint_as_float(uy & 0xffff0000u);                  \
            float lz = v.z - __uint_as_float(uz & 0xffff0000u);                  \
            float lw = v.w - __uint_as_float(uw & 0xffff0000u);                  \
            __nv_bfloat162 l01 = __floats2bfloat162_rn(lx, ly);                  \
            __nv_bfloat162 l23 = __floats2bfloat162_rn(lz, lw);                  \
            *(uint2*)(t + OFF_AHI + so) = make_uint2(hi01, hi23);                \
            *(uint2*)(t + OFF_ALO + so) =                                        \
                make_uint2(*(uint32_t*)&l01, *(uint32_t*)&l23);                  \
        }                                                                        \
        _Pragma("unroll")                                                        \
        for (int j = 0; j < 4; j++) {                                            \
            uint32_t row = (uint32_t)(tid >> 3) + j * 32;                        \
            uint32_t so  = swrow(row, (uint32_t)(tid & 7) * 16);                 \
            *(float4*)(t + OFF_BHI + so) = bh[j];                                \
            *(float4*)(t + OFF_BLO + so) = bl[j];                                \
        }                                                                        \
    } while (0)

    STORE_STAGE(smem);
    __syncthreads();

    const int nChunk = ND / 64;   // 64
#pragma unroll 1
    for (int i = 0; i < nChunk; i++) {
        // prefetch chunk i+1 into regs (overlaps with compute below)
        if (i + 1 < nChunk) {
            const int k0 = (i + 1) * 64;
#pragma unroll
            for (int j = 0; j < 8; j++) av[j] = *(const float4*)(xA + (size_t)j * 16 * ND + k0);
#pragma unroll
            for (int j = 0; j < 4; j++) bh[j] = *(const float4*)(bHp + (size_t)j * 32 * ND + k0);
#pragma unroll
            for (int j = 0; j < 4; j++) bl[j] = *(const float4*)(bLp + (size_t)j * 32 * ND + k0);
        }

        const uint32_t tb  = sbase + (uint32_t)(i & 1) * STAGE_BYTES;
        const uint32_t tAH = tb + OFF_AHI;
        const uint32_t tAL = tb + OFF_ALO;
        const uint32_t tBH = tb + OFF_BHI;
        const uint32_t tBL = tb + OFF_BLO;

#pragma unroll
        for (int ks = 0; ks < 4; ks++) {
            const uint32_t ktA = ((uint32_t)(ks * 32) + kselA) ^ mask;
            const uint32_t ktB = ((uint32_t)(ks * 32) + kselB) ^ mask;

            uint32_t ah[2][4], al[2][4];
            LDSM4(ah[0][0], ah[0][1], ah[0][2], ah[0][3], tAH + aoff0 + ktA);
            LDSM4(ah[1][0], ah[1][1], ah[1][2], ah[1][3], tAH + aoff1 + ktA);
            LDSM4(al[0][0], al[0][1], al[0][2], al[0][3], tAL + aoff0 + ktA);
            LDSM4(al[1][0], al[1][1], al[1][2], al[1][3], tAL + aoff1 + ktA);

            uint32_t bhf[8][2], blf[8][2];
#pragma unroll
            for (int p = 0; p < 4; p++) {
                LDSM4(bhf[2*p][0], bhf[2*p][1], bhf[2*p+1][0], bhf[2*p+1][1],
                      tBH + boff[p] + ktB);
                LDSM4(blf[2*p][0], blf[2*p][1], blf[2*p+1][0], blf[2*p+1][1],
                      tBL + boff[p] + ktB);
            }
#pragma unroll
            for (int mf = 0; mf < 2; mf++)
#pragma unroll
                for (int nf = 0; nf < 8; nf++) {
                    MMA16816(acc[mf][nf], ah[mf], bhf[nf]);
                    MMA16816(acc[mf][nf], ah[mf], blf[nf]);
                    MMA16816(acc[mf][nf], al[mf], bhf[nf]);
                }
        }

        // store next chunk into the OTHER buffer; single barrier per iteration
        // (compute reads buf i, store writes buf i+1 -> no conflict; the
        //  barrier only gates compute i+1 on store completion)
        if (i + 1 < nChunk) {
            STORE_STAGE(smem + ((i + 1) & 1) * STAGE_BYTES);
            __syncthreads();
        }
    }

    // epilogue: bias + relu -> g_h
#pragma unroll
    for (int nf = 0; nf < 8; nf++) {
        const int n = wn + nf * 8 + (lane & 3) * 2;
        const float bn0 = b1[n], bn1 = b1[n + 1];
#pragma unroll
        for (int mf = 0; mf < 2; mf++) {
            const int m = m0 + wm + mf * 16 + qr;
            float2 v0, v1;
            v0.x = fmaxf(acc[mf][nf][0] + bn0, 0.f);
            v0.y = fmaxf(acc[mf][nf][1] + bn1, 0.f);
            v1.x = fmaxf(acc[mf][nf][2] + bn0, 0.f);
            v1.y = fmaxf(acc[mf][nf][3] + bn1, 0.f);
            *(float2*)&g_h[(size_t)m * NH + n]       = v0;
            *(float2*)&g_h[(size_t)(m + 8) * NH + n] = v1;
        }
    }
#undef STORE_STAGE
}

// ---------------------------------------------------------------------------
// Kernel 2: routing. One warp per row, 16 rows per 512-thread block.
// Dynamic smem: W2 (32KB) + hm (40KB) = 72KB, 3 CTAs/SM.
// ---------------------------------------------------------------------------
#define ROUT_SMEM ((NH * NE + 16 * NS * NH) * 4)   // 73728

__global__ __launch_bounds__(512, 3)
void routing_kernel(const float* __restrict__ W2,
                    const float* __restrict__ b2,
                    const float* __restrict__ m1,
                    const float* __restrict__ m2,
                    float* __restrict__ out)
{
    extern __shared__ float rsm[];
    float* W2s = rsm;                 // [NH*NE]
    float* hm  = rsm + NH * NE;       // [16][NS][NH]

    const int tid  = threadIdx.x;
    const int warp = tid >> 5;
    const int lane = tid & 31;

    for (int i = tid; i < NH * NE / 4; i += 512)
        ((float4*)W2s)[i] = ((const float4*)W2)[i];
    __syncthreads();

    const int row = blockIdx.x * 16 + warp;
    float* hw = hm + warp * (NS * NH);

    for (int idx = lane; idx < NS * NH; idx += 32) {
        const int s  = idx >> 7;
        const int hh = idx & 127;
        const float hv = g_h[(size_t)row * NH + hh];
        const float u  = m1[(size_t)s * NB * NH + (size_t)row * NH + hh];
        hw[idx] = (u >= PDROP_F) ? hv * SCALE_F : 0.f;
    }
    __syncwarp();

    const int e0 = lane * 2;

    float lg[NS][2];
#pragma unroll
    for (int s = 0; s < NS; s++) { lg[s][0] = 0.f; lg[s][1] = 0.f; }

    // hh pairs: broadcast float2 LDS on h, two float2 on W2 per pair
#pragma unroll 2
    for (int hh = 0; hh < NH; hh += 2) {
        const float2 w0 = *(const float2*)&W2s[hh * NE + e0];
        const float2 w1 = *(const float2*)&W2s[(hh + 1) * NE + e0];
#pragma unroll
        for (int s = 0; s < NS; s++) {
            const float2 h2 = *(const float2*)&hw[s * NH + hh];
            lg[s][0] = fmaf(h2.y, w1.x, fmaf(h2.x, w0.x, lg[s][0]));
            lg[s][1] = fmaf(h2.y, w1.y, fmaf(h2.x, w0.y, lg[s][1]));
        }
    }

    const float b20 = b2[e0], b21 = b2[e0 + 1];
#pragma unroll
    for (int s = 0; s < NS; s++) {
        float u0 = m2[(size_t)s * NB * NE + (size_t)row * NE + e0];
        float u1 = m2[(size_t)s * NB * NE + (size_t)row * NE + e0 + 1];
        lg[s][0] = (u0 >= PDROP_F) ? (lg[s][0] + b20) * SCALE_F : 0.f;
        lg[s][1] = (u1 >= PDROP_F) ? (lg[s][1] + b21) * SCALE_F : 0.f;
    }

    // mean logits -> softmax
    float ml0 = 0.f, ml1 = 0.f;
#pragma unroll
    for (int s = 0; s < NS; s++) { ml0 += lg[s][0]; ml1 += lg[s][1]; }
    ml0 *= 0.2f; ml1 *= 0.2f;

    float mx = fmaxf(ml0, ml1);
#pragma unroll
    for (int o = 16; o; o >>= 1) mx = fmaxf(mx, __shfl_xor_sync(~0u, mx, o));
    float p0 = __expf(ml0 - mx), p1 = __expf(ml1 - mx);
    float sm = p0 + p1;
#pragma unroll
    for (int o = 16; o; o >>= 1) sm += __shfl_xor_sync(~0u, sm, o);
    const float inv = 1.f / sm;
    p0 *= inv; p1 *= inv;

    // per-sample softmax
    float ap[NS][2];
#pragma unroll
    for (int s = 0; s < NS; s++) {
        float a0 = lg[s][0], a1 = lg[s][1];
        float m = fmaxf(a0, a1);
#pragma unroll
        for (int o = 16; o; o >>= 1) m = fmaxf(m, __shfl_xor_sync(~0u, m, o));
        float e0v = __expf(a0 - m), e1v = __expf(a1 - m);
        float s2 = e0v + e1v;
#pragma unroll
        for (int o = 16; o; o >>= 1) s2 += __shfl_xor_sync(~0u, s2, o);
        const float iv = 1.f / s2;
        ap[s][0] = e0v * iv; ap[s][1] = e1v * iv;
    }

    // uncertainty = mean_e( std_s(ap, ddof=1) )
    float up = 0.f;
#pragma unroll
    for (int j = 0; j < 2; j++) {
        float mean = 0.f;
#pragma unroll
        for (int s = 0; s < NS; s++) mean += ap[s][j];
        mean *= 0.2f;
        float var = 0.f;
#pragma unroll
        for (int s = 0; s < NS; s++) {
            const float d = ap[s][j] - mean;
            var = fmaf(d, d, var);
        }
        up += sqrtf(var * 0.25f);
    }
#pragma unroll
    for (int o = 16; o; o >>= 1) up += __shfl_xor_sync(~0u, up, o);
    const float unc = up * (1.f / 64.f);

    // top-4 (desc, ties -> lower index)
    float v0 = p0, v1 = p1;
    float selp[4]; int seli[4];
#pragma unroll
    for (int t = 0; t < 4; t++) {
        float bv; int bi;
        if (v0 >= v1) { bv = v0; bi = e0; } else { bv = v1; bi = e0 + 1; }
#pragma unroll
        for (int o = 16; o; o >>= 1) {
            const float ov = __shfl_xor_sync(~0u, bv, o);
            const int   oi = __shfl_xor_sync(~0u, bi, o);
            if (ov > bv || (ov == bv && oi < bi)) { bv = ov; bi = oi; }
        }
        selp[t] = bv; seli[t] = bi;
        if (bi == e0)          v0 = -1.f;
        else if (bi == e0 + 1) v1 = -1.f;
    }

    if (lane == 0) {
        const bool un = unc > UNC_T;
        out[row * 4 + 0] = (float)seli[0];
        out[row * 4 + 1] = (float)seli[1];
        out[row * 4 + 2] = un ? (float)seli[2] : -1.f;
        out[row * 4 + 3] = un ? (float)seli[3] : -1.f;
        float* op = out + (size_t)NB * 4;
        op[row * 4 + 0] = selp[0];
        op[row * 4 + 1] = selp[1];
        op[row * 4 + 2] = un ? selp[2] : 0.f;
        op[row * 4 + 3] = un ? selp[3] : 0.f;
        out[(size_t)NB * 8 + row] = unc;
    }
}

// ---------------------------------------------------------------------------
extern "C" void kernel_launch(void* const* d_in, const int* in_sizes, int n_in,
                              void* d_out, int out_size)
{
    const float* x  = (const float*)d_in[0];
    const float* W1 = (const float*)d_in[1];
    const float* b1 = (const float*)d_in[2];
    const float* W2 = (const float*)d_in[3];
    const float* b2 = (const float*)d_in[4];
    const float* m1 = (const float*)d_in[5];
    const float* m2 = (const float*)d_in[6];
    float* out = (float*)d_out;

    cudaFuncSetAttribute(gemm1_hmma, cudaFuncAttributeMaxDynamicSharedMemorySize, GEMM_SMEM);
    cudaFuncSetAttribute(routing_kernel, cudaFuncAttributeMaxDynamicSharedMemorySize, ROUT_SMEM);

    w1split_kernel<<<dim3(ND / 32, NH / 32), 256>>>(W1);
    gemm1_hmma<<<NB / 128, 256, GEMM_SMEM>>>(x, b1);
    routing_kernel<<<NB / 16, 512, ROUT_SMEM>>>(W2, b2, m1, m2, out);
}

// round 15
// speedup vs baseline: 2.9243x; 1.1090x over previous
#include <cuda_runtime.h>
#include <cuda_bf16.h>
#include <stdint.h>
#include <math.h>

#define NB 16384
#define ND 4096
#define NH 128
#define NE 64
#define NS 5

#define SCALE_F 1.4285714626312256f   // float32(1/0.7)
#define PDROP_F 0.3f
#define UNC_T   0.3f

// scratch
__device__ float         g_h[NB * NH];         // hidden activations (8 MB)
__device__ __nv_bfloat16 g_w1t_hi[NH * ND];    // W1^T hi split (1 MB)
__device__ __nv_bfloat16 g_w1t_lo[NH * ND];    // W1^T lo split (1 MB)
__device__ __nv_bfloat16 g_w2t_hi[NE * NH];    // W2^T hi split [E][H]
__device__ __nv_bfloat16 g_w2t_lo[NE * NH];    // W2^T lo split [E][H]

// ---------------------------------------------------------------------------
// PTX helpers (standard ISA, valid on base sm_103 target)
// ---------------------------------------------------------------------------
#define MMA16816(c, a, b) \
    asm volatile("mma.sync.aligned.m16n8k16.row.col.f32.bf16.bf16.f32 " \
        "{%0,%1,%2,%3}, {%4,%5,%6,%7}, {%8,%9}, {%0,%1,%2,%3};" \
        : "+f"((c)[0]), "+f"((c)[1]), "+f"((c)[2]), "+f"((c)[3]) \
        : "r"((a)[0]), "r"((a)[1]), "r"((a)[2]), "r"((a)[3]), \
          "r"((b)[0]), "r"((b)[1]))

#define LDSM4(r0, r1, r2, r3, addr) \
    asm volatile("ldmatrix.sync.aligned.m8n8.x4.shared.b16 {%0,%1,%2,%3}, [%4];" \
        : "=r"(r0), "=r"(r1), "=r"(r2), "=r"(r3) : "r"(addr))

__device__ __forceinline__ uint32_t smem_u32(const void* p) {
    uint32_t a;
    asm("{ .reg .u64 t; cvta.to.shared.u64 t, %1; cvt.u32.u64 %0, t; }" : "=r"(a) : "l"(p));
    return a;
}

// swizzled byte offset of (row, kbyte) in a [rows][128B] tile.
__device__ __forceinline__ uint32_t swrow(uint32_t row, uint32_t kb) {
    return row * 128u + (kb ^ ((row & 7u) << 4));
}

// split one fp32 4-vector into hi/lo bf16 uint2 pair
__device__ __forceinline__ void split4(float4 v, uint2* hi, uint2* lo) {
    uint32_t ux = __float_as_uint(v.x), uy = __float_as_uint(v.y);
    uint32_t uz = __float_as_uint(v.z), uw = __float_as_uint(v.w);
    hi->x = __byte_perm(ux, uy, 0x7632);
    hi->y = __byte_perm(uz, uw, 0x7632);
    float lx = v.x - __uint_as_float(ux & 0xffff0000u);
    float ly = v.y - __uint_as_float(uy & 0xffff0000u);
    float lz = v.z - __uint_as_float(uz & 0xffff0000u);
    float lw = v.w - __uint_as_float(uw & 0xffff0000u);
    __nv_bfloat162 l01 = __floats2bfloat162_rn(lx, ly);
    __nv_bfloat162 l23 = __floats2bfloat162_rn(lz, lw);
    lo->x = *(uint32_t*)&l01;
    lo->y = *(uint32_t*)&l23;
}

// ---------------------------------------------------------------------------
// Kernel 0a: split-transpose W1 [D,H] fp32 -> W1t hi/lo [H,D] bf16
// ---------------------------------------------------------------------------
__global__ void w1split_kernel(const float* __restrict__ W1)
{
    __shared__ unsigned short thi[32][33];
    __shared__ unsigned short tlo[32][33];
    const int k0 = blockIdx.x * 32;     // D tile
    const int n0 = blockIdx.y * 32;     // H tile
    const int c  = threadIdx.x & 31;
    const int r0 = threadIdx.x >> 5;

#pragma unroll
    for (int j = 0; j < 4; j++) {
        const int r = r0 + j * 8;
        float v = W1[(size_t)(k0 + r) * NH + n0 + c];
        uint32_t u = __float_as_uint(v);
        thi[r][c] = (unsigned short)(u >> 16);
        float lo = v - __uint_as_float(u & 0xffff0000u);
        __nv_bfloat16 lb = __float2bfloat16_rn(lo);
        tlo[r][c] = *(unsigned short*)&lb;
    }
    __syncthreads();

    const int c2 = threadIdx.x & 15;
    const int r1 = threadIdx.x >> 4;
#pragma unroll
    for (int j = 0; j < 2; j++) {
        const int n = r1 + j * 16;
        uint32_t hi = (uint32_t)thi[c2 * 2][n] | ((uint32_t)thi[c2 * 2 + 1][n] << 16);
        uint32_t lo = (uint32_t)tlo[c2 * 2][n] | ((uint32_t)tlo[c2 * 2 + 1][n] << 16);
        *(uint32_t*)&g_w1t_hi[(size_t)(n0 + n) * ND + k0 + c2 * 2] = hi;
        *(uint32_t*)&g_w1t_lo[(size_t)(n0 + n) * ND + k0 + c2 * 2] = lo;
    }
}

// ---------------------------------------------------------------------------
// Kernel 0b: split-transpose W2 [H,E] fp32 -> W2t hi/lo [E,H] bf16
// grid (H/32, E/32) = (4, 2)
// ---------------------------------------------------------------------------
__global__ void w2split_kernel(const float* __restrict__ W2)
{
    __shared__ unsigned short thi[32][33];
    __shared__ unsigned short tlo[32][33];
    const int k0 = blockIdx.x * 32;     // H tile (becomes K)
    const int n0 = blockIdx.y * 32;     // E tile (becomes rows)
    const int c  = threadIdx.x & 31;
    const int r0 = threadIdx.x >> 5;

#pragma unroll
    for (int j = 0; j < 4; j++) {
        const int r = r0 + j * 8;
        float v = W2[(size_t)(k0 + r) * NE + n0 + c];
        uint32_t u = __float_as_uint(v);
        thi[r][c] = (unsigned short)(u >> 16);
        float lo = v - __uint_as_float(u & 0xffff0000u);
        __nv_bfloat16 lb = __float2bfloat16_rn(lo);
        tlo[r][c] = *(unsigned short*)&lb;
    }
    __syncthreads();

    const int c2 = threadIdx.x & 15;
    const int r1 = threadIdx.x >> 4;
#pragma unroll
    for (int j = 0; j < 2; j++) {
        const int n = r1 + j * 16;
        uint32_t hi = (uint32_t)thi[c2 * 2][n] | ((uint32_t)thi[c2 * 2 + 1][n] << 16);
        uint32_t lo = (uint32_t)tlo[c2 * 2][n] | ((uint32_t)tlo[c2 * 2 + 1][n] << 16);
        *(uint32_t*)&g_w2t_hi[(size_t)(n0 + n) * NH + k0 + c2 * 2] = hi;
        *(uint32_t*)&g_w2t_lo[(size_t)(n0 + n) * NH + k0 + c2 * 2] = lo;
    }
}

// ---------------------------------------------------------------------------
// Kernel 1: HMMA bf16 3-split GEMM: h = relu(x @ W1 + b1)  (unchanged, proven)
// ---------------------------------------------------------------------------
#define OFF_AHI 0
#define OFF_ALO 16384
#define OFF_BHI 32768
#define OFF_BLO 49152
#define STAGE_BYTES 65536
#define GEMM_SMEM (2 * STAGE_BYTES)   // 131072

__global__ __launch_bounds__(256, 1)
void gemm1_hmma(const float* __restrict__ x, const float* __restrict__ b1)
{
    extern __shared__ __align__(1024) char smem[];
    const uint32_t sbase = smem_u32(smem);
    const int tid  = threadIdx.x;
    const int wid  = tid >> 5;
    const int lane = tid & 31;
    const int m0   = blockIdx.x * 128;

    const int qr = lane >> 2;
    const int wm = (wid & 3) * 32;
    const int wn = (wid >> 2) * 64;

    const uint32_t mask   = (uint32_t)(lane & 7) << 4;
    const uint32_t kselA  = (lane & 16) ? 16u : 0u;
    const uint32_t kselB  = (lane & 8)  ? 16u : 0u;
    const uint32_t rowA0  = (uint32_t)(wm + (lane & 7) + ((lane & 8) ? 8 : 0));
    const uint32_t rowB0  = (uint32_t)(wn + (lane & 7) + ((lane & 16) ? 8 : 0));
    const uint32_t aoff0  = rowA0 * 128u;
    const uint32_t aoff1  = aoff0 + 16u * 128u;
    uint32_t boff[4];
#pragma unroll
    for (int p = 0; p < 4; p++) boff[p] = (rowB0 + p * 16u) * 128u;

    const float*         xA  = x + (size_t)(m0 + (tid >> 4)) * ND + (tid & 15) * 4;
    const __nv_bfloat16* bHp = g_w1t_hi + (size_t)(tid >> 3) * ND + (tid & 7) * 8;
    const __nv_bfloat16* bLp = g_w1t_lo + (size_t)(tid >> 3) * ND + (tid & 7) * 8;

    float acc[2][8][4];
#pragma unroll
    for (int mf = 0; mf < 2; mf++)
#pragma unroll
        for (int nf = 0; nf < 8; nf++)
#pragma unroll
            for (int c = 0; c < 4; c++) acc[mf][nf][c] = 0.f;

    float4 av[8], bh[4], bl[4];

#pragma unroll
    for (int j = 0; j < 8; j++) av[j] = *(const float4*)(xA + (size_t)j * 16 * ND);
#pragma unroll
    for (int j = 0; j < 4; j++) bh[j] = *(const float4*)(bHp + (size_t)j * 32 * ND);
#pragma unroll
    for (int j = 0; j < 4; j++) bl[j] = *(const float4*)(bLp + (size_t)j * 32 * ND);

#define STORE_STAGE(TILE)                                                        \
    do {                                                                         \
        char* t = (TILE);                                                        \
        _Pragma("unroll")                                                        \
        for (int j = 0; j < 8; j++) {                                            \
            uint32_t row = (uint32_t)(tid >> 4) + j * 16;                        \
            uint32_t so  = swrow(row, (uint32_t)(tid & 15) * 8);                 \
            uint2 hi2, lo2;                                                      \
            split4(av[j], &hi2, &lo2);                                           \
            *(uint2*)(t + OFF_AHI + so) = hi2;                                   \
            *(uint2*)(t + OFF_ALO + so) = lo2;                                   \
        }                                                                        \
        _Pragma("unroll")                                                        \
        for (int j = 0; j < 4; j++) {                                            \
            uint32_t row = (uint32_t)(tid >> 3) + j * 32;                        \
            uint32_t so  = swrow(row, (uint32_t)(tid & 7) * 16);                 \
            *(float4*)(t + OFF_BHI + so) = bh[j];                                \
            *(float4*)(t + OFF_BLO + so) = bl[j];                                \
        }                                                                        \
    } while (0)

    STORE_STAGE(smem);
    __syncthreads();

    const int nChunk = ND / 64;   // 64
#pragma unroll 1
    for (int i = 0; i < nChunk; i++) {
        if (i + 1 < nChunk) {
            const int k0 = (i + 1) * 64;
#pragma unroll
            for (int j = 0; j < 8; j++) av[j] = *(const float4*)(xA + (size_t)j * 16 * ND + k0);
#pragma unroll
            for (int j = 0; j < 4; j++) bh[j] = *(const float4*)(bHp + (size_t)j * 32 * ND + k0);
#pragma unroll
            for (int j = 0; j < 4; j++) bl[j] = *(const float4*)(bLp + (size_t)j * 32 * ND + k0);
        }

        const uint32_t tb  = sbase + (uint32_t)(i & 1) * STAGE_BYTES;
        const uint32_t tAH = tb + OFF_AHI;
        const uint32_t tAL = tb + OFF_ALO;
        const uint32_t tBH = tb + OFF_BHI;
        const uint32_t tBL = tb + OFF_BLO;

#pragma unroll
        for (int ks = 0; ks < 4; ks++) {
            const uint32_t ktA = ((uint32_t)(ks * 32) + kselA) ^ mask;
            const uint32_t ktB = ((uint32_t)(ks * 32) + kselB) ^ mask;

            uint32_t ah[2][4], al[2][4];
            LDSM4(ah[0][0], ah[0][1], ah[0][2], ah[0][3], tAH + aoff0 + ktA);
            LDSM4(ah[1][0], ah[1][1], ah[1][2], ah[1][3], tAH + aoff1 + ktA);
            LDSM4(al[0][0], al[0][1], al[0][2], al[0][3], tAL + aoff0 + ktA);
            LDSM4(al[1][0], al[1][1], al[1][2], al[1][3], tAL + aoff1 + ktA);

            uint32_t bhf[8][2], blf[8][2];
#pragma unroll
            for (int p = 0; p < 4; p++) {
                LDSM4(bhf[2*p][0], bhf[2*p][1], bhf[2*p+1][0], bhf[2*p+1][1],
                      tBH + boff[p] + ktB);
                LDSM4(blf[2*p][0], blf[2*p][1], blf[2*p+1][0], blf[2*p+1][1],
                      tBL + boff[p] + ktB);
            }
#pragma unroll
            for (int mf = 0; mf < 2; mf++)
#pragma unroll
                for (int nf = 0; nf < 8; nf++) {
                    MMA16816(acc[mf][nf], ah[mf], bhf[nf]);
                    MMA16816(acc[mf][nf], ah[mf], blf[nf]);
                    MMA16816(acc[mf][nf], al[mf], bhf[nf]);
                }
        }

        if (i + 1 < nChunk) {
            STORE_STAGE(smem + ((i + 1) & 1) * STAGE_BYTES);
            __syncthreads();
        }
    }

#pragma unroll
    for (int nf = 0; nf < 8; nf++) {
        const int n = wn + nf * 8 + (lane & 3) * 2;
        const float bn0 = b1[n], bn1 = b1[n + 1];
#pragma unroll
        for (int mf = 0; mf < 2; mf++) {
            const int m = m0 + wm + mf * 16 + qr;
            float2 v0, v1;
            v0.x = fmaxf(acc[mf][nf][0] + bn0, 0.f);
            v0.y = fmaxf(acc[mf][nf][1] + bn1, 0.f);
            v1.x = fmaxf(acc[mf][nf][2] + bn0, 0.f);
            v1.y = fmaxf(acc[mf][nf][3] + bn1, 0.f);
            *(float2*)&g_h[(size_t)m * NH + n]       = v0;
            *(float2*)&g_h[(size_t)(m + 8) * NH + n] = v1;
        }
    }
#undef STORE_STAGE
}

// ---------------------------------------------------------------------------
// Kernel 2: routing v2 — HMMA logits. 128 CTAs x 128 rows, 256 threads.
// SMEM: A hi/lo [2 chunks][128][128B] (64KB), B hi/lo [2][64][128B] (32KB),
//       logits [128][72] fp32 (36KB), b2 copy (256B). Total ~132.3KB.
// Per sample: build masked-h tiles -> 3-split HMMA -> logits smem ->
// per-thread stats (rows: tid>>1, col-half: tid&1).
// ---------------------------------------------------------------------------
#define R2_A_HI 0
#define R2_A_LO 32768
#define R2_B_HI 65536
#define R2_B_LO 81920
#define R2_LG   98304
#define R2_B2   (R2_LG + 128 * 72 * 4)      // 135168
#define R2_SMEM (R2_B2 + 256)               // 135424

__global__ __launch_bounds__(256, 1)
void routing2_kernel(const float* __restrict__ b2,
                     const float* __restrict__ m1,
                     const float* __restrict__ m2,
                     float* __restrict__ out)
{
    extern __shared__ __align__(1024) char smem[];
    const uint32_t sbase = smem_u32(smem);
    const int tid  = threadIdx.x;
    const int wid  = tid >> 5;
    const int lane = tid & 31;
    const int b0   = blockIdx.x * 128;

    const int qr = lane >> 2;
    const int wm = (wid & 3) * 32;      // warp M offset (rows)
    const int wn = (wid >> 2) * 32;     // warp N offset (experts)

    const uint32_t mask   = (uint32_t)(lane & 7) << 4;
    const uint32_t kselA  = (lane & 16) ? 16u : 0u;
    const uint32_t kselB  = (lane & 8)  ? 16u : 0u;
    const uint32_t aoff0  = (uint32_t)(wm + (lane & 7) + ((lane & 8) ? 8 : 0)) * 128u;
    const uint32_t aoff1  = aoff0 + 16u * 128u;
    const uint32_t rowB0  = (uint32_t)(wn + (lane & 7) + ((lane & 16) ? 8 : 0));
    const uint32_t boff0  = rowB0 * 128u;
    const uint32_t boff1  = (rowB0 + 16u) * 128u;

    float* LG  = (float*)(smem + R2_LG);
    float* b2s = (float*)(smem + R2_B2);

    // stage b2
    if (tid < 64) b2s[tid] = b2[tid];

    // stage W2t hi/lo once: per chunk c: 64 rows x 8 float4
    for (int i = tid; i < 2 * 512; i += 256) {
        const int c  = i >> 9;
        const int rm = i & 511;
        const int e  = rm >> 3;
        const int f4 = rm & 7;
        const uint32_t so = swrow((uint32_t)e, (uint32_t)f4 * 16) + c * 8192;
        *(float4*)(smem + R2_B_HI + so) =
            *(const float4*)(g_w2t_hi + (size_t)e * NH + c * 64 + f4 * 8);
        *(float4*)(smem + R2_B_LO + so) =
            *(const float4*)(g_w2t_lo + (size_t)e * NH + c * 64 + f4 * 8);
    }

    // per-thread stats state: row r = tid>>1, cols ch*32..+31
    const int r  = tid >> 1;
    const int ch = tid & 1;
    const int e0b = ch * 32;

    float slg[32], sp[32], sp2[32];
#pragma unroll
    for (int j = 0; j < 32; j++) { slg[j] = 0.f; sp[j] = 0.f; sp2[j] = 0.f; }

    const float* hrow = g_h + (size_t)(b0 + r) * NH + ch * 64;

#pragma unroll 1
    for (int s = 0; s < NS; s++) {
        // ---- build masked A tiles (thread: row r, k-chunk ch)
        {
            const float* mrow = m1 + (size_t)s * NB * NH + (size_t)(b0 + r) * NH + ch * 64;
            char* tAH = smem + R2_A_HI + ch * 16384;
            char* tAL = smem + R2_A_LO + ch * 16384;
#pragma unroll
            for (int j = 0; j < 16; j++) {
                float4 hv = *(const float4*)(hrow + j * 4);
                float4 uv = *(const float4*)(mrow + j * 4);
                float4 hm;
                hm.x = (uv.x >= PDROP_F) ? hv.x * SCALE_F : 0.f;
                hm.y = (uv.y >= PDROP_F) ? hv.y * SCALE_F : 0.f;
                hm.z = (uv.z >= PDROP_F) ? hv.z * SCALE_F : 0.f;
                hm.w = (uv.w >= PDROP_F) ? hv.w * SCALE_F : 0.f;
                uint2 hi2, lo2;
                split4(hm, &hi2, &lo2);
                const uint32_t so = swrow((uint32_t)r, (uint32_t)j * 8);
                *(uint2*)(tAH + so) = hi2;
                *(uint2*)(tAL + so) = lo2;
            }
        }
        __syncthreads();   // A (and on s==0: B, b2) ready

        // ---- GEMM: [128x128] @ [128x64] -> acc
        float acc[2][4][4];
#pragma unroll
        for (int mf = 0; mf < 2; mf++)
#pragma unroll
            for (int nf = 0; nf < 4; nf++)
#pragma unroll
                for (int c = 0; c < 4; c++) acc[mf][nf][c] = 0.f;

#pragma unroll
        for (int c = 0; c < 2; c++) {
            const uint32_t tAH = sbase + R2_A_HI + c * 16384;
            const uint32_t tAL = sbase + R2_A_LO + c * 16384;
            const uint32_t tBH = sbase + R2_B_HI + c * 8192;
            const uint32_t tBL = sbase + R2_B_LO + c * 8192;
#pragma unroll
            for (int ks = 0; ks < 4; ks++) {
                const uint32_t ktA = ((uint32_t)(ks * 32) + kselA) ^ mask;
                const uint32_t ktB = ((uint32_t)(ks * 32) + kselB) ^ mask;

                uint32_t ah[2][4], al[2][4];
                LDSM4(ah[0][0], ah[0][1], ah[0][2], ah[0][3], tAH + aoff0 + ktA);
                LDSM4(ah[1][0], ah[1][1], ah[1][2], ah[1][3], tAH + aoff1 + ktA);
                LDSM4(al[0][0], al[0][1], al[0][2], al[0][3], tAL + aoff0 + ktA);
                LDSM4(al[1][0], al[1][1], al[1][2], al[1][3], tAL + aoff1 + ktA);

                uint32_t bhf[4][2], blf[4][2];
                LDSM4(bhf[0][0], bhf[0][1], bhf[1][0], bhf[1][1], tBH + boff0 + ktB);
                LDSM4(bhf[2][0], bhf[2][1], bhf[3][0], bhf[3][1], tBH + boff1 + ktB);
                LDSM4(blf[0][0], blf[0][1], blf[1][0], blf[1][1], tBL + boff0 + ktB);
                LDSM4(blf[2][0], blf[2][1], blf[3][0], blf[3][1], tBL + boff1 + ktB);
#pragma unroll
                for (int mf = 0; mf < 2; mf++)
#pragma unroll
                    for (int nf = 0; nf < 4; nf++) {
                        MMA16816(acc[mf][nf], ah[mf], bhf[nf]);
                        MMA16816(acc[mf][nf], ah[mf], blf[nf]);
                        MMA16816(acc[mf][nf], al[mf], bhf[nf]);
                    }
            }
        }

        // ---- store logits fragments to smem [128][72]
#pragma unroll
        for (int mf = 0; mf < 2; mf++)
#pragma unroll
            for (int nf = 0; nf < 4; nf++) {
                const int rw = wm + mf * 16 + qr;
                const int cl = wn + nf * 8 + (lane & 3) * 2;
                *(float2*)&LG[rw * 72 + cl]       = make_float2(acc[mf][nf][0], acc[mf][nf][1]);
                *(float2*)&LG[(rw + 8) * 72 + cl] = make_float2(acc[mf][nf][2], acc[mf][nf][3]);
            }
        __syncthreads();   // logits ready (also fences stats(s-1) before overwrite)

        // ---- stats: mask2 + bias, per-sample softmax, accumulate
        {
            float lgb[32];
            const float* Lrow  = LG + r * 72 + e0b;
            const float* m2row = m2 + (size_t)s * NB * NE + (size_t)(b0 + r) * NE + e0b;
#pragma unroll
            for (int j4 = 0; j4 < 8; j4++) {
                float4 raw = *(const float4*)(Lrow + j4 * 4);
                float4 u   = *(const float4*)(m2row + j4 * 4);
                const float* bb = b2s + e0b + j4 * 4;
                lgb[j4*4+0] = (u.x >= PDROP_F) ? (raw.x + bb[0]) * SCALE_F : 0.f;
                lgb[j4*4+1] = (u.y >= PDROP_F) ? (raw.y + bb[1]) * SCALE_F : 0.f;
                lgb[j4*4+2] = (u.z >= PDROP_F) ? (raw.z + bb[2]) * SCALE_F : 0.f;
                lgb[j4*4+3] = (u.w >= PDROP_F) ? (raw.w + bb[3]) * SCALE_F : 0.f;
            }
            float mx = lgb[0];
#pragma unroll
            for (int j = 1; j < 32; j++) mx = fmaxf(mx, lgb[j]);
            mx = fmaxf(mx, __shfl_xor_sync(~0u, mx, 1));
            float se = 0.f;
#pragma unroll
            for (int j = 0; j < 32; j++) {
                slg[j] += lgb[j];
                float e = __expf(lgb[j] - mx);
                lgb[j] = e;
                se += e;
            }
            se += __shfl_xor_sync(~0u, se, 1);
            const float inv = 1.f / se;
#pragma unroll
            for (int j = 0; j < 32; j++) {
                const float p = lgb[j] * inv;
                sp[j] += p;
                sp2[j] = fmaf(p, p, sp2[j]);
            }
        }
        // no trailing sync: next iteration's post-build-A sync orders stats
        // before the next logits overwrite.
    }

    // ---- finalize: mean-logits softmax, uncertainty, top-4
    float pr[32];
    {
        float mx;
        {
            float t0 = slg[0];
#pragma unroll
            for (int j = 1; j < 32; j++) t0 = fmaxf(t0, slg[j]);
            mx = t0 * 0.2f;
        }
        mx = fmaxf(mx, __shfl_xor_sync(~0u, mx, 1));
        float se = 0.f;
#pragma unroll
        for (int j = 0; j < 32; j++) {
            float e = __expf(slg[j] * 0.2f - mx);
            pr[j] = e;
            se += e;
        }
        se += __shfl_xor_sync(~0u, se, 1);
        const float inv = 1.f / se;
#pragma unroll
        for (int j = 0; j < 32; j++) pr[j] *= inv;
    }

    float up = 0.f;
#pragma unroll
    for (int j = 0; j < 32; j++) {
        // ddof=1: var = (Σp² − (Σp)²/5) / 4
        float var = (sp2[j] - sp[j] * sp[j] * 0.2f) * 0.25f;
        up += sqrtf(fmaxf(var, 0.f));
    }
    up += __shfl_xor_sync(~0u, up, 1);
    const float unc = up * (1.f / 64.f);

    // top-4 over the row (pair of threads), desc, ties -> lower index
    float selp[4]; int seli[4];
#pragma unroll
    for (int t = 0; t < 4; t++) {
        float bv = pr[0]; int bi = e0b;
#pragma unroll
        for (int j = 1; j < 32; j++)
            if (pr[j] > bv) { bv = pr[j]; bi = e0b + j; }
        const float ov = __shfl_xor_sync(~0u, bv, 1);
        const int   oi = __shfl_xor_sync(~0u, bi, 1);
        if (ov > bv || (ov == bv && oi < bi)) { bv = ov; bi = oi; }
        selp[t] = bv; seli[t] = bi;
        if ((bi >> 5) == ch) pr[bi & 31] = -1.f;
    }

    if (ch == 0) {
        const int row = b0 + r;
        const bool un = unc > UNC_T;
        out[row * 4 + 0] = (float)seli[0];
        out[row * 4 + 1] = (float)seli[1];
        out[row * 4 + 2] = un ? (float)seli[2] : -1.f;
        out[row * 4 + 3] = un ? (float)seli[3] : -1.f;
        float* op = out + (size_t)NB * 4;
        op[row * 4 + 0] = selp[0];
        op[row * 4 + 1] = selp[1];
        op[row * 4 + 2] = un ? selp[2] : 0.f;
        op[row * 4 + 3] = un ? selp[3] : 0.f;
        out[(size_t)NB * 8 + row] = unc;
    }
}

// ---------------------------------------------------------------------------
extern "C" void kernel_launch(void* const* d_in, const int* in_sizes, int n_in,
                              void* d_out, int out_size)
{
    const float* x  = (const float*)d_in[0];
    const float* W1 = (const float*)d_in[1];
    const float* b1 = (const float*)d_in[2];
    const float* W2 = (const float*)d_in[3];
    const float* b2 = (const float*)d_in[4];
    const float* m1 = (const float*)d_in[5];
    const float* m2 = (const float*)d_in[6];
    float* out = (float*)d_out;

    cudaFuncSetAttribute(gemm1_hmma, cudaFuncAttributeMaxDynamicSharedMemorySize, GEMM_SMEM);
    cudaFuncSetAttribute(routing2_kernel, cudaFuncAttributeMaxDynamicSharedMemorySize, R2_SMEM);

    w1split_kernel<<<dim3(ND / 32, NH / 32), 256>>>(W1);
    w2split_kernel<<<dim3(NH / 32, NE / 32), 256>>>(W2);
    gemm1_hmma<<<NB / 128, 256, GEMM_SMEM>>>(x, b1);
    routing2_kernel<<<NB / 128, 256, R2_SMEM>>>(b2, m1, m2, out);
}